// round 6
// baseline (speedup 1.0000x reference)
#include <cuda_runtime.h>
#include <cstdint>

// x_ref, x : [B=4, C=3, H=512, W=512] float32
// out: [4,3,512,512] f32 (3145728) then best_shifts [4,2] as floats (8)

#define NIMG   12
#define HH     512
#define WW     512
#define W4     (WW/4)
#define NSHIFT 81
#define IMG_ELEMS (HH*WW)
#define OUT_IMG   (NIMG*IMG_ELEMS)
#define NBLK   768           // 12 imgs * 64 blocks (8 rows per block)
#define BLK_PER_BATCH 192    // 3 imgs * 64

__device__ float  g_partial[NBLK * NSHIFT];
__device__ int2   g_best[4];
__device__ float4 g_zero4;          // zero-initialized; never written

// ---- packed f32x2 helpers -------------------------------------------------
__device__ __forceinline__ uint64_t pk2(float lo, float hi) {
    uint64_t r;
    asm("mov.b64 %0, {%1, %2};" : "=l"(r) : "f"(lo), "f"(hi));
    return r;
}
__device__ __forceinline__ void upk2(float& lo, float& hi, uint64_t v) {
    asm("mov.b64 {%0, %1}, %2;" : "=f"(lo), "=f"(hi) : "l"(v));
}
__device__ __forceinline__ void ffma2(uint64_t& d, uint64_t a, uint64_t b) {
    asm("fma.rn.f32x2 %0, %1, %2, %3;" : "=l"(d) : "l"(a), "l"(b), "l"(d));
}

// ---------------------------------------------------------------------------
// Phase 1: 81-shift correlation, direct read from x_ref, packed-f32x2 FMA.
// Thread: 2 rows x 8 cols; dx-outer; acc = 4 f32x2 pairs + 1 scalar.
// Block = 256 thr = 4 rowpairs x 64 strips; 64 blocks per image.
// ---------------------------------------------------------------------------
__global__ void __launch_bounds__(256, 3) corr_kernel(const float* __restrict__ x,
                                                      const float* __restrict__ xref) {
    __shared__ float ssum[NSHIFT];
    if (threadIdx.x < NSHIFT) ssum[threadIdx.x] = 0.0f;
    __syncthreads();

    int img    = blockIdx.x >> 6;
    int rowblk = blockIdx.x & 63;
    int strip  = threadIdx.x & 63;
    int rpair  = threadIdx.x >> 6;
    int a0     = rowblk * 8 + rpair * 2;
    int j0     = strip * 8;
    int lane   = threadIdx.x & 31;

    // preload x strip: 2 rows x 8 cols
    const float4* xp4 = (const float4*)x + (size_t)img * HH * W4;
    float xv[16];
#pragma unroll
    for (int r = 0; r < 2; r++) {
        float4 m0 = __ldg(xp4 + (a0 + r) * W4 + (j0 >> 2));
        float4 m1 = __ldg(xp4 + (a0 + r) * W4 + (j0 >> 2) + 1);
        xv[r * 8 + 0] = m0.x; xv[r * 8 + 1] = m0.y;
        xv[r * 8 + 2] = m0.z; xv[r * 8 + 3] = m0.w;
        xv[r * 8 + 4] = m1.x; xv[r * 8 + 5] = m1.y;
        xv[r * 8 + 6] = m1.z; xv[r * 8 + 7] = m1.w;
    }
    // dx-invariant broadcast pairs {xv, xv}
    uint64_t xx[16];
#pragma unroll
    for (int k = 0; k < 16; k++) xx[k] = pk2(xv[k], xv[k]);

    const bool leftok  = (strip != 0);
    const bool rightok = (strip != 63);
    const float4* zp   = &g_zero4;
    // row pointer for (dx=0, r=0): padded row a0-4, float4 col (j0/4)-1
    const float4* rrow = (const float4*)xref + (size_t)img * HH * W4
                         + (ptrdiff_t)(a0 - 4) * W4 + (j0 >> 2) - 1;

#pragma unroll 1
    for (int dx = 0; dx < 9; dx++) {
        uint64_t a01 = 0ull, a23 = 0ull, a45 = 0ull, a67 = 0ull;
        float a8 = 0.0f;

#pragma unroll
        for (int r = 0; r < 2; r++) {
            int ar = a0 + r + dx - 4;
            bool rowok = (unsigned)ar < (unsigned)HH;
            const float4* rp = rrow + r * W4;
            float4 q0 = __ldg((rowok && leftok)  ? rp     : zp);
            float4 q1 = __ldg( rowok             ? rp + 1 : zp);
            float4 q2 = __ldg( rowok             ? rp + 2 : zp);
            float4 q3 = __ldg((rowok && rightok) ? rp + 3 : zp);
            float rv[16] = {q0.x, q0.y, q0.z, q0.w, q1.x, q1.y, q1.z, q1.w,
                            q2.x, q2.y, q2.z, q2.w, q3.x, q3.y, q3.z, q3.w};
            // even pairs {rv[2k],rv[2k+1]} and odd pairs {rv[2k+1],rv[2k+2]}
            uint64_t e[8], o[7];
#pragma unroll
            for (int k = 0; k < 8; k++) e[k] = pk2(rv[2 * k], rv[2 * k + 1]);
#pragma unroll
            for (int k = 0; k < 7; k++) o[k] = pk2(rv[2 * k + 1], rv[2 * k + 2]);

#pragma unroll
            for (int p = 0; p < 8; p++) {
                uint64_t xp = xx[r * 8 + p];
                if ((p & 1) == 0) {
                    int h = p >> 1;
                    ffma2(a01, xp, e[h + 0]);
                    ffma2(a23, xp, e[h + 1]);
                    ffma2(a45, xp, e[h + 2]);
                    ffma2(a67, xp, e[h + 3]);
                } else {
                    int h = (p - 1) >> 1;
                    ffma2(a01, xp, o[h + 0]);
                    ffma2(a23, xp, o[h + 1]);
                    ffma2(a45, xp, o[h + 2]);
                    ffma2(a67, xp, o[h + 3]);
                }
                a8 = fmaf(xv[r * 8 + p], rv[p + 8], a8);
            }
        }

        // unpack accumulators and reduce across the warp
        float acc[9];
        upk2(acc[0], acc[1], a01);
        upk2(acc[2], acc[3], a23);
        upk2(acc[4], acc[5], a45);
        upk2(acc[6], acc[7], a67);
        acc[8] = a8;
#pragma unroll
        for (int d = 0; d < 9; d++) {
            float v = acc[d];
            v += __shfl_xor_sync(0xffffffffu, v, 16);
            v += __shfl_xor_sync(0xffffffffu, v, 8);
            v += __shfl_xor_sync(0xffffffffu, v, 4);
            v += __shfl_xor_sync(0xffffffffu, v, 2);
            v += __shfl_xor_sync(0xffffffffu, v, 1);
            int s = dx * 9 + d;
            if (lane == (s & 31)) atomicAdd(&ssum[s], v);
        }
        rrow += W4;
    }

    __syncthreads();
    if (threadIdx.x < NSHIFT)
        g_partial[blockIdx.x * NSHIFT + threadIdx.x] = ssum[threadIdx.x];
}

// ---------------------------------------------------------------------------
// Phase 2: deterministic reduce of 192 partials per (batch,shift) + argmax.
// ---------------------------------------------------------------------------
__global__ void __launch_bounds__(384) reduce_argmax_kernel(float* __restrict__ d_out,
                                                            int out_size) {
    __shared__ float sims[4 * NSHIFT];
    int t = threadIdx.x;
    if (t < 4 * NSHIFT) {
        int b = t / NSHIFT;
        int s = t - b * NSHIFT;
        const float* pp = g_partial + (size_t)b * BLK_PER_BATCH * NSHIFT + s;
        float acc = 0.0f;
#pragma unroll 8
        for (int i = 0; i < BLK_PER_BATCH; i++) acc += pp[i * NSHIFT];
        sims[t] = acc;
    }
    __syncthreads();

    int w = t >> 5, lane = t & 31;
    if (w < 4) {
        float bv = -3.0e38f;
        int bi = NSHIFT;
        for (int s = lane; s < NSHIFT; s += 32) {
            float v = sims[w * NSHIFT + s];
            if (v > bv || (v == bv && s < bi)) { bv = v; bi = s; }
        }
#pragma unroll
        for (int off = 16; off; off >>= 1) {
            float ov = __shfl_xor_sync(0xffffffffu, bv, off);
            int   oi = __shfl_xor_sync(0xffffffffu, bi, off);
            if (ov > bv || (ov == bv && oi < bi)) { bv = ov; bi = oi; }
        }
        if (lane == 0) {
            int sx = bi / 9 - 4;
            int sy = bi % 9 - 4;
            g_best[w] = make_int2(sx, sy);
            if (out_size >= OUT_IMG + 8) {
                d_out[OUT_IMG + w * 2 + 0] = (float)sx;
                d_out[OUT_IMG + w * 2 + 1] = (float)sy;
            }
        }
    }
}

// ---------------------------------------------------------------------------
// Phase 3: apply best shift. 2 aligned LDG.128 + warp-uniform extract.
// ---------------------------------------------------------------------------
__global__ void __launch_bounds__(256) apply_kernel(const float* __restrict__ x,
                                                    float* __restrict__ out) {
    int t = blockIdx.x * 256 + threadIdx.x;      // float4 index
    int base = t << 2;
    int j0  = base & 511;
    int i   = (base >> 9) & 511;
    int img = base >> 18;
    int b   = img / 3;
    int2 s  = g_best[b];
    int si  = i - s.x;
    float4 v = make_float4(0.f, 0.f, 0.f, 0.f);
    if ((unsigned)si < (unsigned)HH) {
        int sj  = j0 - s.y;
        int sa  = sj & ~3;
        int off = sj & 3;
        const float* row = x + ((size_t)img << 18) + (si << 9);
        float4 qa = ((unsigned)sa < (unsigned)WW)
                        ? __ldg((const float4*)(row + sa)) : v;
        float4 qb = ((unsigned)(sa + 4) < (unsigned)WW)
                        ? __ldg((const float4*)(row + sa + 4)) : v;
        switch (off) {
            case 0:  v = qa; break;
            case 1:  v = make_float4(qa.y, qa.z, qa.w, qb.x); break;
            case 2:  v = make_float4(qa.z, qa.w, qb.x, qb.y); break;
            default: v = make_float4(qa.w, qb.x, qb.y, qb.z); break;
        }
    }
    ((float4*)out)[t] = v;
}

// ---------------------------------------------------------------------------
extern "C" void kernel_launch(void* const* d_in, const int* in_sizes, int n_in,
                              void* d_out, int out_size) {
    const float* x_ref = (const float*)d_in[0];
    const float* x     = (const float*)d_in[1];
    float* out = (float*)d_out;

    corr_kernel<<<NBLK, 256>>>(x, x_ref);
    reduce_argmax_kernel<<<1, 384>>>(out, out_size);
    apply_kernel<<<OUT_IMG / 4 / 256, 256>>>(x, out);
}

// round 7
// speedup vs baseline: 1.2678x; 1.2678x over previous
#include <cuda_runtime.h>

// x_ref, x : [B=4, C=3, H=512, W=512] float32
// out: [4,3,512,512] f32 (3145728) then best_shifts [4,2] as floats (8)

#define NIMG   12
#define HH     512
#define WW     512
#define W4     (WW/4)
#define PROWS  520          // 4-row halo each side
#define PADW   520          // 4-col halo each side
#define PADW4  (PADW/4)     // 130
#define NSHIFT 81
#define IMG_ELEMS (HH*WW)
#define OUT_IMG   (NIMG*IMG_ELEMS)
#define NBLK   384          // 12 imgs * 32 blocks
#define BLK_PER_BATCH 96    // 3 imgs * 32

__device__ float4 g_refpad[NIMG * PROWS * PADW4];   // ~13 MB zero-padded ref
__device__ float  g_partial[NBLK * NSHIFT];
__device__ int2   g_best[4];

// ---------------------------------------------------------------------------
// Phase 0: zero-padded ref copy. Interior is a straight float4 copy
// (pc4 in [1,128], pr in [4,515]); edges are zeroed.
// ---------------------------------------------------------------------------
__global__ void __launch_bounds__(256) prep_kernel(const float* __restrict__ xref) {
    int idx = blockIdx.x * 256 + threadIdx.x;
    const int total4 = NIMG * PROWS * PADW4;     // 811200
    if (idx >= total4) return;
    int pc4 = idx % PADW4;
    int pr  = (idx / PADW4) % PROWS;
    int img = idx / (PADW4 * PROWS);
    int srow = pr - 4;
    float4 v = make_float4(0.f, 0.f, 0.f, 0.f);
    if ((unsigned)srow < (unsigned)HH && pc4 >= 1 && pc4 <= 128) {
        // c0 = pc4*4 - 4 in [0,508], 16B aligned
        v = __ldg((const float4*)(xref + ((size_t)img * HH + srow) * WW) + (pc4 - 1));
    }
    g_refpad[idx] = v;
}

// ---------------------------------------------------------------------------
// Phase 1: 81-shift correlation on the padded ref (branch-free hot loop).
// Thread: 4 rows x 8 cols; dx-outer; 9 live accumulators; 2592 FMAs/thread.
// Block = 256 thr = 4 rowgroups x 64 strips; 32 blocks per image.
// __launch_bounds__(256,2): allow up to 128 regs -> NO spills.
// ---------------------------------------------------------------------------
__global__ void __launch_bounds__(256, 2) corr_kernel(const float* __restrict__ x) {
    __shared__ float ssum[NSHIFT];
    if (threadIdx.x < NSHIFT) ssum[threadIdx.x] = 0.0f;
    __syncthreads();

    int img   = blockIdx.x >> 5;
    int strip = threadIdx.x & 63;
    int rgrp  = ((blockIdx.x & 31) << 2) + (threadIdx.x >> 6);
    int a0    = rgrp * 4;
    int j0    = strip * 8;
    int lane  = threadIdx.x & 31;

    // preload x strip: 4 rows x 8 cols (32 regs)
    const float4* xp4 = (const float4*)x + (size_t)img * HH * W4;
    float xv[32];
#pragma unroll
    for (int r = 0; r < 4; r++) {
        float4 m0 = __ldg(xp4 + (a0 + r) * W4 + (j0 >> 2));
        float4 m1 = __ldg(xp4 + (a0 + r) * W4 + (j0 >> 2) + 1);
        xv[r * 8 + 0] = m0.x; xv[r * 8 + 1] = m0.y;
        xv[r * 8 + 2] = m0.z; xv[r * 8 + 3] = m0.w;
        xv[r * 8 + 4] = m1.x; xv[r * 8 + 5] = m1.y;
        xv[r * 8 + 6] = m1.z; xv[r * 8 + 7] = m1.w;
    }

    // running row pointer: (dx=0, r=0) touches padded row a0, padded col j0
    const float4* rrow = g_refpad + (size_t)img * PROWS * PADW4
                         + (size_t)a0 * PADW4 + (j0 >> 2);

#pragma unroll 1
    for (int dx = 0; dx < 9; dx++) {
        float acc[9];
#pragma unroll
        for (int d = 0; d < 9; d++) acc[d] = 0.0f;

#pragma unroll
        for (int r = 0; r < 4; r++) {
            const float4* rp = rrow + r * PADW4;
            float4 q0 = rp[0], q1 = rp[1], q2 = rp[2], q3 = rp[3];
            float rv[16] = {q0.x, q0.y, q0.z, q0.w, q1.x, q1.y, q1.z, q1.w,
                            q2.x, q2.y, q2.z, q2.w, q3.x, q3.y, q3.z, q3.w};
#pragma unroll
            for (int p = 0; p < 8; p++) {
#pragma unroll
                for (int d = 0; d < 9; d++) {
                    acc[d] += xv[r * 8 + p] * rv[p + d];
                }
            }
        }

        // warp butterfly per dy, then one-lane atomic into block smem
#pragma unroll
        for (int d = 0; d < 9; d++) {
            float v = acc[d];
            v += __shfl_xor_sync(0xffffffffu, v, 16);
            v += __shfl_xor_sync(0xffffffffu, v, 8);
            v += __shfl_xor_sync(0xffffffffu, v, 4);
            v += __shfl_xor_sync(0xffffffffu, v, 2);
            v += __shfl_xor_sync(0xffffffffu, v, 1);
            int s = dx * 9 + d;
            if (lane == (s & 31)) atomicAdd(&ssum[s], v);
        }
        rrow += PADW4;
    }

    __syncthreads();
    if (threadIdx.x < NSHIFT)
        g_partial[blockIdx.x * NSHIFT + threadIdx.x] = ssum[threadIdx.x];
}

// ---------------------------------------------------------------------------
// Phase 2: deterministic reduce of 96 partials per (batch,shift) + argmax
// (first-max tie-break, matching jnp.argmax).
// ---------------------------------------------------------------------------
__global__ void __launch_bounds__(384) reduce_argmax_kernel(float* __restrict__ d_out,
                                                            int out_size) {
    __shared__ float sims[4 * NSHIFT];
    int t = threadIdx.x;
    if (t < 4 * NSHIFT) {
        int b = t / NSHIFT;
        int s = t - b * NSHIFT;
        const float* pp = g_partial + (size_t)b * BLK_PER_BATCH * NSHIFT + s;
        float acc = 0.0f;
#pragma unroll 8
        for (int i = 0; i < BLK_PER_BATCH; i++) acc += pp[i * NSHIFT];
        sims[t] = acc;
    }
    __syncthreads();

    int w = t >> 5, lane = t & 31;
    if (w < 4) {
        float bv = -3.0e38f;
        int bi = NSHIFT;
        for (int s = lane; s < NSHIFT; s += 32) {
            float v = sims[w * NSHIFT + s];
            if (v > bv || (v == bv && s < bi)) { bv = v; bi = s; }
        }
#pragma unroll
        for (int off = 16; off; off >>= 1) {
            float ov = __shfl_xor_sync(0xffffffffu, bv, off);
            int   oi = __shfl_xor_sync(0xffffffffu, bi, off);
            if (ov > bv || (ov == bv && oi < bi)) { bv = ov; bi = oi; }
        }
        if (lane == 0) {
            int sx = bi / 9 - 4;
            int sy = bi % 9 - 4;
            g_best[w] = make_int2(sx, sy);
            if (out_size >= OUT_IMG + 8) {
                d_out[OUT_IMG + w * 2 + 0] = (float)sx;
                d_out[OUT_IMG + w * 2 + 1] = (float)sy;
            }
        }
    }
}

// ---------------------------------------------------------------------------
// Phase 3: apply best shift. 2 aligned LDG.128 + warp-uniform extract.
// ---------------------------------------------------------------------------
__global__ void __launch_bounds__(256) apply_kernel(const float* __restrict__ x,
                                                    float* __restrict__ out) {
    int t = blockIdx.x * 256 + threadIdx.x;      // float4 index
    int base = t << 2;
    int j0  = base & 511;
    int i   = (base >> 9) & 511;
    int img = base >> 18;
    int b   = img / 3;
    int2 s  = g_best[b];
    int si  = i - s.x;
    float4 v = make_float4(0.f, 0.f, 0.f, 0.f);
    if ((unsigned)si < (unsigned)HH) {
        int sj  = j0 - s.y;
        int sa  = sj & ~3;
        int off = sj & 3;                        // warp-uniform
        const float* row = x + ((size_t)img << 18) + (si << 9);
        float4 qa = ((unsigned)sa < (unsigned)WW)
                        ? __ldg((const float4*)(row + sa)) : v;
        float4 qb = ((unsigned)(sa + 4) < (unsigned)WW)
                        ? __ldg((const float4*)(row + sa + 4)) : v;
        switch (off) {
            case 0:  v = qa; break;
            case 1:  v = make_float4(qa.y, qa.z, qa.w, qb.x); break;
            case 2:  v = make_float4(qa.z, qa.w, qb.x, qb.y); break;
            default: v = make_float4(qa.w, qb.x, qb.y, qb.z); break;
        }
    }
    ((float4*)out)[t] = v;
}

// ---------------------------------------------------------------------------
extern "C" void kernel_launch(void* const* d_in, const int* in_sizes, int n_in,
                              void* d_out, int out_size) {
    const float* x_ref = (const float*)d_in[0];
    const float* x     = (const float*)d_in[1];
    float* out = (float*)d_out;

    {
        int total4 = NIMG * PROWS * PADW4;
        prep_kernel<<<(total4 + 255) / 256, 256>>>(x_ref);
    }
    corr_kernel<<<NBLK, 256>>>(x);
    reduce_argmax_kernel<<<1, 384>>>(out, out_size);
    apply_kernel<<<OUT_IMG / 4 / 256, 256>>>(x, out);
}

// round 8
// speedup vs baseline: 1.2746x; 1.0054x over previous
#include <cuda_runtime.h>

// x_ref, x : [B=4, C=3, H=512, W=512] float32
// out: [4,3,512,512] f32 (3145728) then best_shifts [4,2] as floats (8)

#define NIMG   12
#define HH     512
#define WW     512
#define W4     (WW/4)        // 128
#define NSHIFT 81
#define IMG_ELEMS (HH*WW)    // 262144 floats = 65536 float4
#define OUT_IMG   (NIMG*IMG_ELEMS)
#define NBLK   768           // 12 imgs * 64 blocks (8 rows per block)
#define BLK_PER_BATCH 192    // 3 imgs * 64
#define TROWS  16            // 8 tile rows + 4 halo each side
#define TCOLS4 130           // 520 padded cols / 4

__device__ float g_partial[NBLK * NSHIFT];
__device__ int2  g_best[4];

// ---------------------------------------------------------------------------
// Phase 1: 81-shift correlation. Ref tile staged in smem (zero-padded halo,
// edge predicates only in staging). Hot loop: unconditional LDS.128 + FFMA.
// Thread: 2 rows x 8 cols; dx-outer; 9 live accumulators; 1296 FMAs/thread.
// Block = 256 thr = 4 rowpairs x 64 strips; covers 8 image rows.
// ---------------------------------------------------------------------------
__global__ void __launch_bounds__(256) corr_kernel(const float* __restrict__ x,
                                                   const float* __restrict__ xref) {
    __shared__ float4 tile[TROWS * TCOLS4];   // 33280 B
    __shared__ float  ssum[NSHIFT];

    int t = threadIdx.x;
    if (t < NSHIFT) ssum[t] = 0.0f;

    int img      = blockIdx.x >> 6;           // 64 blocks per image
    int rowblk   = blockIdx.x & 63;
    int rowstart = rowblk * 8;

    // ---- stage zero-padded ref tile: rows [rowstart-4, rowstart+12),
    //      cols [-4, 516) ----
    {
        int tc = t & 31, tr = t >> 5;
        const float* refimg = xref + ((size_t)img << 18);
#pragma unroll
        for (int pr = tr; pr < TROWS; pr += 8) {
            int grow = rowstart + pr - 4;
            bool rok = (unsigned)grow < (unsigned)HH;
            const float4* src = (const float4*)(refimg + ((size_t)(grow & 511) << 9));
#pragma unroll
            for (int pc4 = tc; pc4 < TCOLS4; pc4 += 32) {
                float4 v = make_float4(0.f, 0.f, 0.f, 0.f);
                if (rok && pc4 >= 1 && pc4 <= 128) v = __ldg(src + (pc4 - 1));
                tile[pr * TCOLS4 + pc4] = v;
            }
        }
    }
    __syncthreads();

    int strip = t & 63;
    int rpair = t >> 6;
    int lr0   = rpair * 2;
    int a0    = rowstart + lr0;
    int j0    = strip * 8;
    int lane  = t & 31;

    // preload x strip: 2 rows x 8 cols
    const float4* xp4 = (const float4*)x + ((size_t)img << 16);
    float xv[16];
#pragma unroll
    for (int r = 0; r < 2; r++) {
        float4 m0 = __ldg(xp4 + (a0 + r) * W4 + strip * 2);
        float4 m1 = __ldg(xp4 + (a0 + r) * W4 + strip * 2 + 1);
        xv[r * 8 + 0] = m0.x; xv[r * 8 + 1] = m0.y;
        xv[r * 8 + 2] = m0.z; xv[r * 8 + 3] = m0.w;
        xv[r * 8 + 4] = m1.x; xv[r * 8 + 5] = m1.y;
        xv[r * 8 + 6] = m1.z; xv[r * 8 + 7] = m1.w;
    }

    const float4* tbase = tile + lr0 * TCOLS4 + strip * 2;

#pragma unroll 1
    for (int dx = 0; dx < 9; dx++) {
        float acc[9];
#pragma unroll
        for (int d = 0; d < 9; d++) acc[d] = 0.0f;

#pragma unroll
        for (int r = 0; r < 2; r++) {
            const float4* rp = tbase + (r + dx) * TCOLS4;
            float4 q0 = rp[0], q1 = rp[1], q2 = rp[2], q3 = rp[3];
            float rv[16] = {q0.x, q0.y, q0.z, q0.w, q1.x, q1.y, q1.z, q1.w,
                            q2.x, q2.y, q2.z, q2.w, q3.x, q3.y, q3.z, q3.w};
#pragma unroll
            for (int p = 0; p < 8; p++) {
#pragma unroll
                for (int d = 0; d < 9; d++) {
                    acc[d] += xv[r * 8 + p] * rv[p + d];
                }
            }
        }

        // warp butterfly per dy, then one-lane atomic into block smem
#pragma unroll
        for (int d = 0; d < 9; d++) {
            float v = acc[d];
            v += __shfl_xor_sync(0xffffffffu, v, 16);
            v += __shfl_xor_sync(0xffffffffu, v, 8);
            v += __shfl_xor_sync(0xffffffffu, v, 4);
            v += __shfl_xor_sync(0xffffffffu, v, 2);
            v += __shfl_xor_sync(0xffffffffu, v, 1);
            int s = dx * 9 + d;
            if (lane == (s & 31)) atomicAdd(&ssum[s], v);
        }
    }

    __syncthreads();
    if (t < NSHIFT)
        g_partial[blockIdx.x * NSHIFT + t] = ssum[t];
}

// ---------------------------------------------------------------------------
// Phase 2: deterministic reduce of 192 partials per (batch,shift) + argmax
// (first-max tie-break, matching jnp.argmax).
// ---------------------------------------------------------------------------
__global__ void __launch_bounds__(384) reduce_argmax_kernel(float* __restrict__ d_out,
                                                            int out_size) {
    __shared__ float sims[4 * NSHIFT];
    int t = threadIdx.x;
    if (t < 4 * NSHIFT) {
        int b = t / NSHIFT;
        int s = t - b * NSHIFT;
        const float* pp = g_partial + (size_t)b * BLK_PER_BATCH * NSHIFT + s;
        float acc = 0.0f;
#pragma unroll 8
        for (int i = 0; i < BLK_PER_BATCH; i++) acc += pp[i * NSHIFT];
        sims[t] = acc;
    }
    __syncthreads();

    int w = t >> 5, lane = t & 31;
    if (w < 4) {
        float bv = -3.0e38f;
        int bi = NSHIFT;
        for (int s = lane; s < NSHIFT; s += 32) {
            float v = sims[w * NSHIFT + s];
            if (v > bv || (v == bv && s < bi)) { bv = v; bi = s; }
        }
#pragma unroll
        for (int off = 16; off; off >>= 1) {
            float ov = __shfl_xor_sync(0xffffffffu, bv, off);
            int   oi = __shfl_xor_sync(0xffffffffu, bi, off);
            if (ov > bv || (ov == bv && oi < bi)) { bv = ov; bi = oi; }
        }
        if (lane == 0) {
            int sx = bi / 9 - 4;
            int sy = bi % 9 - 4;
            g_best[w] = make_int2(sx, sy);
            if (out_size >= OUT_IMG + 8) {
                d_out[OUT_IMG + w * 2 + 0] = (float)sx;
                d_out[OUT_IMG + w * 2 + 1] = (float)sy;
            }
        }
    }
}

// ---------------------------------------------------------------------------
// Phase 3: apply best shift. 16 floats per thread: 5 aligned LDG.128 +
// warp-uniform extract -> 4 STG.128. Aligned 4-col blocks are entirely in or
// out of [0,512), so block-granular zeroing gives exact element masking.
// ---------------------------------------------------------------------------
__global__ void __launch_bounds__(256) apply_kernel(const float* __restrict__ x,
                                                    float* __restrict__ out) {
    int t = blockIdx.x * 256 + threadIdx.x;
    int base = t << 4;                     // 16 floats per thread
    int j0  = base & 511;                  // multiple of 16
    int i   = (base >> 9) & 511;
    int img = base >> 18;
    int b   = img / 3;
    int2 s  = g_best[b];
    int si  = i - s.x;

    const float4 z4 = make_float4(0.f, 0.f, 0.f, 0.f);
    float4 o0 = z4, o1 = z4, o2 = z4, o3 = z4;

    if ((unsigned)si < (unsigned)HH) {
        int sj0 = j0 - s.y;                // [-4, 500]
        int sa  = sj0 & ~3;
        int off = sj0 & 3;                 // warp-uniform
        const float* row = x + ((size_t)img << 18) + (si << 9);
        float4 q[5];
#pragma unroll
        for (int k = 0; k < 5; k++) {
            int c = sa + 4 * k;            // [-4, 516]
            q[k] = ((unsigned)c < (unsigned)WW) ? __ldg((const float4*)(row + c)) : z4;
        }
        switch (off) {
            case 0:
                o0 = q[0]; o1 = q[1]; o2 = q[2]; o3 = q[3];
                break;
            case 1:
                o0 = make_float4(q[0].y, q[0].z, q[0].w, q[1].x);
                o1 = make_float4(q[1].y, q[1].z, q[1].w, q[2].x);
                o2 = make_float4(q[2].y, q[2].z, q[2].w, q[3].x);
                o3 = make_float4(q[3].y, q[3].z, q[3].w, q[4].x);
                break;
            case 2:
                o0 = make_float4(q[0].z, q[0].w, q[1].x, q[1].y);
                o1 = make_float4(q[1].z, q[1].w, q[2].x, q[2].y);
                o2 = make_float4(q[2].z, q[2].w, q[3].x, q[3].y);
                o3 = make_float4(q[3].z, q[3].w, q[4].x, q[4].y);
                break;
            default:
                o0 = make_float4(q[0].w, q[1].x, q[1].y, q[1].z);
                o1 = make_float4(q[1].w, q[2].x, q[2].y, q[2].z);
                o2 = make_float4(q[2].w, q[3].x, q[3].y, q[3].z);
                o3 = make_float4(q[3].w, q[4].x, q[4].y, q[4].z);
                break;
        }
    }
    float4* op = (float4*)out + (t << 2);
    op[0] = o0; op[1] = o1; op[2] = o2; op[3] = o3;
}

// ---------------------------------------------------------------------------
extern "C" void kernel_launch(void* const* d_in, const int* in_sizes, int n_in,
                              void* d_out, int out_size) {
    const float* x_ref = (const float*)d_in[0];
    const float* x     = (const float*)d_in[1];
    float* out = (float*)d_out;

    corr_kernel<<<NBLK, 256>>>(x, x_ref);
    reduce_argmax_kernel<<<1, 384>>>(out, out_size);
    apply_kernel<<<OUT_IMG / 16 / 256, 256>>>(x, out);
}